// round 8
// baseline (speedup 1.0000x reference)
#include <cuda_runtime.h>
#include <cuda_bf16.h>
#include <math.h>
#include <stdint.h>

typedef __nv_bfloat16 bf16;

#define NTOK 16384
#define CDIM 256
#define HID  1024

// -------- scratch (__device__ globals; no allocations allowed) --------
__device__ float g_xn     [NTOK * CDIM];
__device__ float g_offattn[NTOK * 256];
__device__ float g_xres   [NTOK * CDIM];
__device__ bf16  g_xnb    [NTOK * CDIM];
__device__ bf16  g_vb     [NTOK * CDIM];
__device__ bf16  g_aggb   [NTOK * CDIM];
__device__ bf16  g_yb     [NTOK * CDIM];
__device__ bf16  g_hb     [NTOK * HID];
__device__ bf16  g_h2b    [NTOK * HID];
__device__ bf16  g_wvb    [256 * 256];
__device__ bf16  g_woutb  [256 * 256];
__device__ bf16  g_w1b    [256 * 1024];
__device__ bf16  g_w2b    [1024 * 256];
__device__ float g_wcat   [256 * 256];
__device__ float g_bcat   [256];

__device__ __forceinline__ float gelu_f(float v) {
    return 0.5f * v * (1.0f + erff(v * 0.7071067811865476f));
}

__device__ __forceinline__ uint32_t smem_u32(const void* p) {
    uint32_t a;
    asm("{ .reg .u64 t; cvta.to.shared.u64 t, %1; cvt.u32.u64 %0, t; }" : "=r"(a) : "l"(p));
    return a;
}

__device__ __forceinline__ uint32_t f2tf32(float f) {
    uint32_t r;
    asm("cvt.rna.tf32.f32 %0, %1;" : "=r"(r) : "f"(f));
    return r;
}

// ================= K1: fused prep + LN1 =================
// blocks [0, NTOK): LayerNorm1 (tf32-rounded f32 + bf16 outputs)
// blocks [NTOK, NTOK+2816): weight conversion / concat
__global__ void prep_ln_kernel(
    const float* __restrict__ x, const float* __restrict__ g, const float* __restrict__ b,
    float* __restrict__ xn, bf16* __restrict__ xnb,
    const float* wv, const float* wout, const float* w1, const float* w2,
    const float* w_off, const float* w_attn, const float* b_off, const float* b_attn,
    bf16* wvb, bf16* woutb, bf16* w1b, bf16* w2b, float* wcat, float* bcat) {
    if (blockIdx.x < NTOK) {
        int tok = blockIdx.x;
        int c = threadIdx.x;
        float v = x[(size_t)tok * CDIM + c];
        __shared__ float sh[8];
        float s = v;
        #pragma unroll
        for (int o = 16; o; o >>= 1) s += __shfl_xor_sync(0xffffffffu, s, o);
        if ((c & 31) == 0) sh[c >> 5] = s;
        __syncthreads();
        float tot = 0.f;
        #pragma unroll
        for (int i = 0; i < 8; ++i) tot += sh[i];
        float mean = tot * (1.0f / CDIM);
        __syncthreads();
        float d = v - mean;
        float s2 = d * d;
        #pragma unroll
        for (int o = 16; o; o >>= 1) s2 += __shfl_xor_sync(0xffffffffu, s2, o);
        if ((c & 31) == 0) sh[c >> 5] = s2;
        __syncthreads();
        float v2 = 0.f;
        #pragma unroll
        for (int i = 0; i < 8; ++i) v2 += sh[i];
        float var = v2 * (1.0f / CDIM);
        float out = d * rsqrtf(var + 1e-5f) * g[c] + b[c];
        xn[(size_t)tok * CDIM + c]  = __uint_as_float(f2tf32(out));
        xnb[(size_t)tok * CDIM + c] = __float2bfloat16(out);
        return;
    }
    int i = (blockIdx.x - NTOK) * 256 + threadIdx.x;
    if (i < 65536) { wvb[i] = __float2bfloat16(wv[i]); return; }
    i -= 65536;
    if (i < 65536) { woutb[i] = __float2bfloat16(wout[i]); return; }
    i -= 65536;
    if (i < 262144) { w1b[i] = __float2bfloat16(w1[i]); return; }
    i -= 262144;
    if (i < 262144) { w2b[i] = __float2bfloat16(w2[i]); return; }
    i -= 262144;
    if (i < 65536) {
        int k = i >> 8, col = i & 255;
        float v = (col < 144) ? w_off[k * 144 + col]
                : (col < 216) ? w_attn[k * 72 + (col - 144)] : 0.f;
        wcat[i] = __uint_as_float(f2tf32(v));
        if (k == 0)
            bcat[col] = (col < 144) ? b_off[col]
                      : (col < 216) ? b_attn[col - 144] : 0.f;
    }
}

// ---------------- LayerNorm (LN2 only; f32 in -> bf16 out) -------------------
__global__ void ln_kernel(const float* __restrict__ x, const float* __restrict__ g,
                          const float* __restrict__ b, bf16* __restrict__ yb) {
    int tok = blockIdx.x;
    int c = threadIdx.x;
    float v = x[(size_t)tok * CDIM + c];
    __shared__ float sh[8];
    float s = v;
    #pragma unroll
    for (int o = 16; o; o >>= 1) s += __shfl_xor_sync(0xffffffffu, s, o);
    if ((c & 31) == 0) sh[c >> 5] = s;
    __syncthreads();
    float tot = 0.f;
    #pragma unroll
    for (int i = 0; i < 8; ++i) tot += sh[i];
    float mean = tot * (1.0f / CDIM);
    __syncthreads();
    float d = v - mean;
    float s2 = d * d;
    #pragma unroll
    for (int o = 16; o; o >>= 1) s2 += __shfl_xor_sync(0xffffffffu, s2, o);
    if ((c & 31) == 0) sh[c >> 5] = s2;
    __syncthreads();
    float v2 = 0.f;
    #pragma unroll
    for (int i = 0; i < 8; ++i) v2 += sh[i];
    float var = v2 * (1.0f / CDIM);
    float out = d * rsqrtf(var + 1e-5f) * g[c] + b[c];
    yb[(size_t)tok * CDIM + c] = __float2bfloat16(out);
}

// ---------------- tf32 GEMM device body (off/attn) ---------------------------
#define TFA_STR 20
#define TFB_STR 264
#define TFA_SZ  (64 * TFA_STR * 4)
#define TFB_SZ  (16 * TFB_STR * 4)
#define TF_STG  (TFA_SZ + TFB_SZ)
#define TF_SMEM (3 * TF_STG)

__device__ void tgemm_dev(char* sm_, int mblk,
                          const float* __restrict__ A, const float* __restrict__ Bw,
                          const float* __restrict__ bias, float* __restrict__ C) {
    uint32_t S0 = smem_u32(sm_);
    int t = threadIdx.x;
    int lane = t & 31, warp = t >> 5;
    int wm = (warp & 1) * 32;
    int wn = (warp >> 1) * 64;
    int m0 = mblk * 64;

    int a_row = t >> 2, a_c4 = (t & 3) * 4;
    const float* Ag = A + (size_t)(m0 + a_row) * 256 + a_c4;
    uint32_t a_s = S0 + (a_row * TFA_STR + a_c4) * 4;

    auto prefetch = [&](int it) {
        int st = it % 3;
        const float* ag = Ag + it * 16;
        asm volatile("cp.async.cg.shared.global [%0], [%1], 16;"
                     :: "r"(a_s + st * TF_STG), "l"(ag));
        #pragma unroll
        for (int i = 0; i < 4; ++i) {
            int idx = t + i * 256;
            int row = idx >> 6, c4 = (idx & 63) * 4;
            const float* bg = Bw + (size_t)(it * 16 + row) * 256 + c4;
            uint32_t dst = S0 + TFA_SZ + (row * TFB_STR + c4) * 4 + st * TF_STG;
            asm volatile("cp.async.cg.shared.global [%0], [%1], 16;" :: "r"(dst), "l"(bg));
        }
        asm volatile("cp.async.commit_group;");
    };

    float acc[2][8][4];
    #pragma unroll
    for (int mi = 0; mi < 2; ++mi)
        #pragma unroll
        for (int nj = 0; nj < 8; ++nj)
            #pragma unroll
            for (int r = 0; r < 4; ++r) acc[mi][nj][r] = 0.f;

    const int niter = 16;
    prefetch(0); prefetch(1);

    int lr = lane >> 2, lc = lane & 3;
    for (int it = 0; it < niter; ++it) {
        if (it + 1 < niter) asm volatile("cp.async.wait_group 1;");
        else                asm volatile("cp.async.wait_group 0;");
        __syncthreads();
        if (it + 2 < niter) prefetch(it + 2);

        const uint32_t* As = (const uint32_t*)(sm_ + (it % 3) * TF_STG);
        const uint32_t* Bs = (const uint32_t*)(sm_ + (it % 3) * TF_STG + TFA_SZ);

        #pragma unroll
        for (int kk = 0; kk < 2; ++kk) {
            uint32_t af[2][4];
            #pragma unroll
            for (int mi = 0; mi < 2; ++mi) {
                int rb = wm + mi * 16 + lr;
                af[mi][0] = As[rb * TFA_STR + kk * 8 + lc];
                af[mi][1] = As[(rb + 8) * TFA_STR + kk * 8 + lc];
                af[mi][2] = As[rb * TFA_STR + kk * 8 + lc + 4];
                af[mi][3] = As[(rb + 8) * TFA_STR + kk * 8 + lc + 4];
            }
            #pragma unroll
            for (int nj = 0; nj < 8; ++nj) {
                uint32_t b0 = Bs[(kk * 8 + lc) * TFB_STR + wn + nj * 8 + lr];
                uint32_t b1 = Bs[(kk * 8 + lc + 4) * TFB_STR + wn + nj * 8 + lr];
                #pragma unroll
                for (int mi = 0; mi < 2; ++mi)
                    asm volatile(
                        "mma.sync.aligned.m16n8k8.row.col.f32.tf32.tf32.f32 "
                        "{%0,%1,%2,%3}, {%4,%5,%6,%7}, {%8,%9}, {%0,%1,%2,%3};"
                        : "+f"(acc[mi][nj][0]), "+f"(acc[mi][nj][1]),
                          "+f"(acc[mi][nj][2]), "+f"(acc[mi][nj][3])
                        : "r"(af[mi][0]), "r"(af[mi][1]), "r"(af[mi][2]), "r"(af[mi][3]),
                          "r"(b0), "r"(b1));
            }
        }
    }

    #pragma unroll
    for (int mi = 0; mi < 2; ++mi) {
        #pragma unroll
        for (int nj = 0; nj < 8; ++nj) {
            int r = m0 + wm + mi * 16 + lr;
            int c = wn + nj * 8 + lc * 2;
            float bx = bias[c], by = bias[c + 1];
            float2 v0 = {acc[mi][nj][0] + bx, acc[mi][nj][1] + by};
            float2 v1 = {acc[mi][nj][2] + bx, acc[mi][nj][3] + by};
            *(float2*)(C + (size_t)r * 256 + c) = v0;
            *(float2*)(C + (size_t)(r + 8) * 256 + c) = v1;
        }
    }
}

// ---------------- bf16 mma.sync GEMM device body -----------------------------
#define PBM 128
#define PBN 128
#define PBK 32
#define PASTR 80
#define PBSTR 272
#define PA_ST (PBM * PASTR)
#define PB_ST (PBK * PBSTR)
#define PSTG  (PA_ST + PB_ST)
#define PSMEM (3 * PSTG)
#define FUSED_SMEM (TF_SMEM > PSMEM ? TF_SMEM : PSMEM)

template<int EPI>
__device__ void hgemm_dev(char* sm_, int bx, int by,
                          const bf16* __restrict__ A, const bf16* __restrict__ B,
                          const float* __restrict__ bias, const float* __restrict__ resid,
                          void* __restrict__ Cp, int N, int K) {
    uint32_t S0 = smem_u32(sm_);

    int t = threadIdx.x;
    int lane = t & 31, warp = t >> 5;
    int wm = (warp & 3) * 32;
    int wn = (warp >> 2) * 64;
    int m0 = by * PBM;
    int n0 = bx * PBN;

    int a_row = t >> 1;
    int a_c16 = (t & 1) * 2;
    const bf16* Ag = A + (size_t)(m0 + a_row) * K + a_c16 * 8;
    uint32_t a_s = S0 + a_row * PASTR + a_c16 * 16;
    int b_row = t >> 3;
    int b_c16 = (t & 7) * 2;
    const bf16* Bg = B + (size_t)b_row * N + n0 + b_c16 * 8;
    uint32_t b_s = S0 + PA_ST + b_row * PBSTR + b_c16 * 16;

    auto prefetch = [&](int chunk) {
        int st = chunk % 3;
        const bf16* ag = Ag + chunk * PBK;
        const bf16* bg = Bg + (size_t)chunk * PBK * N;
        uint32_t sa = a_s + st * PSTG;
        uint32_t sb = b_s + st * PSTG;
        asm volatile("cp.async.cg.shared.global [%0], [%1], 16;" :: "r"(sa), "l"(ag));
        asm volatile("cp.async.cg.shared.global [%0], [%1], 16;" :: "r"(sa + 16), "l"(ag + 8));
        asm volatile("cp.async.cg.shared.global [%0], [%1], 16;" :: "r"(sb), "l"(bg));
        asm volatile("cp.async.cg.shared.global [%0], [%1], 16;" :: "r"(sb + 16), "l"(bg + 8));
        asm volatile("cp.async.commit_group;");
    };

    uint32_t aoff[2], boff[4];
    #pragma unroll
    for (int mi = 0; mi < 2; ++mi)
        aoff[mi] = (wm + mi * 16 + (lane & 15)) * PASTR + (lane >> 4) * 16;
    int tile = lane >> 3;
    #pragma unroll
    for (int ni = 0; ni < 4; ++ni)
        boff[ni] = PA_ST + ((tile & 1) * 8 + (lane & 7)) * PBSTR
                 + (wn + ni * 16 + (tile >> 1) * 8) * 2;

    float acc[2][8][4];
    #pragma unroll
    for (int mi = 0; mi < 2; ++mi)
        #pragma unroll
        for (int nj = 0; nj < 8; ++nj)
            #pragma unroll
            for (int r = 0; r < 4; ++r) acc[mi][nj][r] = 0.f;

    int niter = K / PBK;
    prefetch(0);
    prefetch(1);

    for (int it = 0; it < niter; ++it) {
        if (it + 1 < niter) asm volatile("cp.async.wait_group 1;");
        else                asm volatile("cp.async.wait_group 0;");
        __syncthreads();
        if (it + 2 < niter) prefetch(it + 2);

        uint32_t Sb = S0 + (it % 3) * PSTG;
        #pragma unroll
        for (int kk = 0; kk < 2; ++kk) {
            uint32_t a[2][4];
            #pragma unroll
            for (int mi = 0; mi < 2; ++mi) {
                uint32_t addr = Sb + aoff[mi] + kk * 32;
                asm volatile("ldmatrix.sync.aligned.m8n8.x4.shared.b16 {%0,%1,%2,%3}, [%4];"
                    : "=r"(a[mi][0]), "=r"(a[mi][1]), "=r"(a[mi][2]), "=r"(a[mi][3]) : "r"(addr));
            }
            uint32_t bq[4][4];
            #pragma unroll
            for (int ni = 0; ni < 4; ++ni) {
                uint32_t addr = Sb + boff[ni] + kk * 16 * PBSTR;
                asm volatile("ldmatrix.sync.aligned.m8n8.x4.trans.shared.b16 {%0,%1,%2,%3}, [%4];"
                    : "=r"(bq[ni][0]), "=r"(bq[ni][1]), "=r"(bq[ni][2]), "=r"(bq[ni][3]) : "r"(addr));
            }
            #pragma unroll
            for (int mi = 0; mi < 2; ++mi)
                #pragma unroll
                for (int nj = 0; nj < 8; ++nj) {
                    uint32_t b0 = bq[nj >> 1][(nj & 1) * 2];
                    uint32_t b1 = bq[nj >> 1][(nj & 1) * 2 + 1];
                    asm volatile(
                        "mma.sync.aligned.m16n8k16.row.col.f32.bf16.bf16.f32 "
                        "{%0,%1,%2,%3}, {%4,%5,%6,%7}, {%8,%9}, {%0,%1,%2,%3};"
                        : "+f"(acc[mi][nj][0]), "+f"(acc[mi][nj][1]),
                          "+f"(acc[mi][nj][2]), "+f"(acc[mi][nj][3])
                        : "r"(a[mi][0]), "r"(a[mi][1]), "r"(a[mi][2]), "r"(a[mi][3]),
                          "r"(b0), "r"(b1));
                }
        }
    }

    int r_base = m0 + wm + (lane >> 2);
    int c_base = n0 + wn + (lane & 3) * 2;
    #pragma unroll
    for (int mi = 0; mi < 2; ++mi) {
        #pragma unroll
        for (int nj = 0; nj < 8; ++nj) {
            int r = r_base + mi * 16;
            int c = c_base + nj * 8;
            float bx = bias[c], by = bias[c + 1];
            float o00 = acc[mi][nj][0] + bx;
            float o01 = acc[mi][nj][1] + by;
            float o10 = acc[mi][nj][2] + bx;
            float o11 = acc[mi][nj][3] + by;
            if (EPI == 1) {
                o00 = gelu_f(o00); o01 = gelu_f(o01);
                o10 = gelu_f(o10); o11 = gelu_f(o11);
            }
            if (EPI == 2) {
                const float* rp0 = resid + (size_t)r * N + c;
                const float* rp1 = resid + (size_t)(r + 8) * N + c;
                float* Cf = (float*)Cp;
                float2 v0 = {o00 + rp0[0], o01 + rp0[1]};
                float2 v1 = {o10 + rp1[0], o11 + rp1[1]};
                *(float2*)(Cf + (size_t)r * N + c) = v0;
                *(float2*)(Cf + (size_t)(r + 8) * N + c) = v1;
            } else {
                bf16* Cb = (bf16*)Cp;
                __nv_bfloat162 v0 = {__float2bfloat16(o00), __float2bfloat16(o01)};
                __nv_bfloat162 v1 = {__float2bfloat16(o10), __float2bfloat16(o11)};
                *(__nv_bfloat162*)(Cb + (size_t)r * N + c) = v0;
                *(__nv_bfloat162*)(Cb + (size_t)(r + 8) * N + c) = v1;
            }
        }
    }
}

// standalone hgemm launches
template<int EPI>
__global__ __launch_bounds__(256)
void hgemm_kernel(const bf16* __restrict__ A, const bf16* __restrict__ B,
                  const float* __restrict__ bias, const float* __restrict__ resid,
                  void* __restrict__ Cp, int N, int K) {
    extern __shared__ char sm_[];
    hgemm_dev<EPI>(sm_, blockIdx.x, blockIdx.y, A, B, bias, resid, Cp, N, K);
}

// ================= K2: fused v-proj (bf16 TC) + off/attn (tf32 TC) ===========
__global__ __launch_bounds__(256)
void fused_vproj_offattn(const bf16* __restrict__ xnb, const bf16* __restrict__ wvb,
                         const float* __restrict__ b_v, bf16* __restrict__ vb,
                         const float* __restrict__ xn, const float* __restrict__ wcat,
                         const float* __restrict__ bcat, float* __restrict__ offattn) {
    extern __shared__ char sm_[];
    if (blockIdx.z == 0)
        hgemm_dev<0>(sm_, blockIdx.x, blockIdx.y, xnb, wvb, b_v, nullptr, vb, 256, 256);
    else
        tgemm_dev(sm_, blockIdx.y * 2 + blockIdx.x, xn, wcat, bcat, offattn);
}

// ---------------- Deformable sampling: one warp = (token, head-pair) ---------
__global__ void sample_kernel(const bf16* __restrict__ v, const float* __restrict__ offattn,
                              const float* __restrict__ rp, bf16* __restrict__ agg) {
    int gw = blockIdx.x * 8 + (threadIdx.x >> 5);
    int lane = threadIdx.x & 31;
    int tg = gw >> 2;
    int head = ((gw & 3) << 1) + (lane >> 4);
    int l16 = lane & 15;
    int bb = tg >> 13;
    int pos = tg & 8191;

    const float* lg = offattn + (size_t)tg * 256 + 144 + head * 9;
    float w[9];
    float mx = -1e30f;
    #pragma unroll
    for (int k = 0; k < 9; ++k) { w[k] = lg[k]; mx = fmaxf(mx, w[k]); }
    float sum = 0.f;
    #pragma unroll
    for (int k = 0; k < 9; ++k) { w[k] = expf(w[k] - mx); sum += w[k]; }
    float inv = 1.0f / sum;

    const float* rpp  = rp + (size_t)pos * 18;
    const float* offp = offattn + (size_t)tg * 256 + head * 18;
    const __nv_bfloat162* vc = (const __nv_bfloat162*)v + head * 16 + l16;
    int base = bb << 13;
    float a0 = 0.f, a1 = 0.f;
    #pragma unroll
    for (int k = 0; k < 9; ++k) {
        float cx = (rpp[k * 2 + 0] + offp[k * 2 + 0] + 1.0f) * 0.5f * 127.0f;
        float cy = (rpp[k * 2 + 1] + offp[k * 2 + 1] + 1.0f) * 0.5f * 63.0f;
        float fx = floorf(cx), fy = floorf(cy);
        float wx = cx - fx, wy = cy - fy;
        int x0 = min(max((int)fx, 0), 127);
        int x1 = min(max((int)fx + 1, 0), 127);
        int y0 = min(max((int)fy, 0), 63);
        int y1 = min(max((int)fy + 1, 0), 63);
        float2 v00 = __bfloat1622float2(vc[(size_t)(base + y0 * 128 + x0) * 128]);
        float2 v01 = __bfloat1622float2(vc[(size_t)(base + y0 * 128 + x1) * 128]);
        float2 v10 = __bfloat1622float2(vc[(size_t)(base + y1 * 128 + x0) * 128]);
        float2 v11 = __bfloat1622float2(vc[(size_t)(base + y1 * 128 + x1) * 128]);
        float w00 = (1.f - wy) * (1.f - wx), w01 = (1.f - wy) * wx;
        float w10 = wy * (1.f - wx),         w11 = wy * wx;
        float wk = w[k] * inv;
        a0 += (v00.x * w00 + v01.x * w01 + v10.x * w10 + v11.x * w11) * wk;
        a1 += (v00.y * w00 + v01.y * w01 + v10.y * w10 + v11.y * w11) * wk;
    }
    __nv_bfloat162 ov = {__float2bfloat16(a0), __float2bfloat16(a1)};
    *(__nv_bfloat162*)(agg + (size_t)tg * 256 + head * 32 + l16 * 2) = ov;
}

// ---------------- Depthwise 3x3 conv: sliding window, 4-way x-split ----------
__global__ void dwconv_kernel(const bf16* __restrict__ h, const float* __restrict__ wdw,
                              const float* __restrict__ bdw, bf16* __restrict__ o) {
    int c2 = blockIdx.x * 256 + threadIdx.x;
    int y = blockIdx.y & 63;
    int seg = blockIdx.y >> 6;
    int bb = blockIdx.z;
    int c = c2 * 2;
    int x0 = seg * 32;

    float w0[9], w1[9];
    #pragma unroll
    for (int i = 0; i < 9; ++i) { w0[i] = wdw[c * 9 + i]; w1[i] = wdw[(c + 1) * 9 + i]; }
    float bb0 = bdw[c], bb1 = bdw[c + 1];

    const __nv_bfloat162* hp = (const __nv_bfloat162*)h;
    size_t base = ((size_t)(bb << 13) + y * 128) * 512 + c2;
    bool hu = (y > 0), hd = (y < 63);
    __nv_bfloat162 zero = __float2bfloat162_rn(0.f);

    __nv_bfloat162 cm[3], cc[3], cn[3];
    {
        size_t p = base + ((x0 + 127) & 127) * 512;
        cm[0] = hu ? hp[p - 65536] : zero; cm[1] = hp[p]; cm[2] = hd ? hp[p + 65536] : zero;
        p = base + x0 * 512;
        cc[0] = hu ? hp[p - 65536] : zero; cc[1] = hp[p]; cc[2] = hd ? hp[p + 65536] : zero;
    }
    bf16* op = o + ((size_t)(bb << 13) + y * 128) * 1024 + c;

    for (int x = x0; x < x0 + 32; ++x) {
        size_t p = base + ((x + 1) & 127) * 512;
        cn[0] = hu ? hp[p - 65536] : zero; cn[1] = hp[p]; cn[2] = hd ? hp[p + 65536] : zero;

        float a0 = bb0, a1 = bb1;
        #pragma unroll
        for (int dy = 0; dy < 3; ++dy) {
            float2 vm = __bfloat1622float2(cm[dy]);
            float2 vc = __bfloat1622float2(cc[dy]);
            float2 vp = __bfloat1622float2(cn[dy]);
            a0 += vm.x * w0[dy * 3 + 0] + vc.x * w0[dy * 3 + 1] + vp.x * w0[dy * 3 + 2];
            a1 += vm.y * w1[dy * 3 + 0] + vc.y * w1[dy * 3 + 1] + vp.y * w1[dy * 3 + 2];
        }
        __nv_bfloat162 ov = {__float2bfloat16(gelu_f(a0)), __float2bfloat16(gelu_f(a1))};
        *(__nv_bfloat162*)(op + (size_t)x * 1024) = ov;

        #pragma unroll
        for (int i = 0; i < 3; ++i) { cm[i] = cc[i]; cc[i] = cn[i]; }
    }
}

// ---------------- launch ----------------
extern "C" void kernel_launch(void* const* d_in, const int* in_sizes, int n_in,
                              void* d_out, int out_size) {
    const float* x      = (const float*)d_in[0];
    const float* rp     = (const float*)d_in[1];
    const float* ln1_g  = (const float*)d_in[2];
    const float* ln1_b  = (const float*)d_in[3];
    const float* w_v    = (const float*)d_in[4];
    const float* b_v    = (const float*)d_in[5];
    const float* w_off  = (const float*)d_in[6];
    const float* b_off  = (const float*)d_in[7];
    const float* w_attn = (const float*)d_in[8];
    const float* b_attn = (const float*)d_in[9];
    const float* w_out  = (const float*)d_in[10];
    const float* b_out  = (const float*)d_in[11];
    const float* ln2_g  = (const float*)d_in[12];
    const float* ln2_b  = (const float*)d_in[13];
    const float* w1     = (const float*)d_in[14];
    const float* b1     = (const float*)d_in[15];
    const float* w_dw   = (const float*)d_in[16];
    const float* b_dw   = (const float*)d_in[17];
    const float* w2     = (const float*)d_in[18];
    const float* b2     = (const float*)d_in[19];
    float* out = (float*)d_out;

    float *xn, *offattn, *xres, *wcat, *bcat;
    bf16 *xnb, *vb, *aggb, *yb, *hb, *h2b, *wvb, *woutb, *w1b, *w2b;
    cudaGetSymbolAddress((void**)&xn,      g_xn);
    cudaGetSymbolAddress((void**)&offattn, g_offattn);
    cudaGetSymbolAddress((void**)&xres,    g_xres);
    cudaGetSymbolAddress((void**)&wcat,    g_wcat);
    cudaGetSymbolAddress((void**)&bcat,    g_bcat);
    cudaGetSymbolAddress((void**)&xnb,     g_xnb);
    cudaGetSymbolAddress((void**)&vb,      g_vb);
    cudaGetSymbolAddress((void**)&aggb,    g_aggb);
    cudaGetSymbolAddress((void**)&yb,      g_yb);
    cudaGetSymbolAddress((void**)&hb,      g_hb);
    cudaGetSymbolAddress((void**)&h2b,     g_h2b);
    cudaGetSymbolAddress((void**)&wvb,     g_wvb);
    cudaGetSymbolAddress((void**)&woutb,   g_woutb);
    cudaGetSymbolAddress((void**)&w1b,     g_w1b);
    cudaGetSymbolAddress((void**)&w2b,     g_w2b);

    cudaFuncSetAttribute(hgemm_kernel<1>,    cudaFuncAttributeMaxDynamicSharedMemorySize, PSMEM);
    cudaFuncSetAttribute(hgemm_kernel<2>,    cudaFuncAttributeMaxDynamicSharedMemorySize, PSMEM);
    cudaFuncSetAttribute(fused_vproj_offattn, cudaFuncAttributeMaxDynamicSharedMemorySize, FUSED_SMEM);

    // K1: LN1 || weight prep
    prep_ln_kernel<<<NTOK + 2816, 256>>>(
        x, ln1_g, ln1_b, xn, xnb,
        w_v, w_out, w1, w2, w_off, w_attn, b_off, b_attn,
        wvb, woutb, w1b, w2b, wcat, bcat);
    // K2: v projection || offsets+attn
    fused_vproj_offattn<<<dim3(2, 128, 2), 256, FUSED_SMEM>>>(
        xnb, wvb, b_v, vb, xn, wcat, bcat, offattn);
    // K3: softmax + bilinear sampling + aggregation
    sample_kernel<<<NTOK / 2, 256>>>(vb, offattn, rp, aggb);
    // K4: output proj + residual -> xres (f32)
    hgemm_kernel<2><<<dim3(256 / PBN, NTOK / PBM), 256, PSMEM>>>(aggb, woutb, b_out, x, xres, 256, 256);
    // K5: LN2 -> yb (bf16)
    ln_kernel<<<NTOK, 256>>>(xres, ln2_g, ln2_b, yb);
    // K6: fc1 + GELU
    hgemm_kernel<1><<<dim3(HID / PBN, NTOK / PBM), 256, PSMEM>>>(yb, w1b, b1, nullptr, hb, HID, 256);
    // K7: depthwise conv + GELU
    dwconv_kernel<<<dim3(2, 256, 2), 256>>>(hb, w_dw, b_dw, h2b);
    // K8: fc2 + residual -> out (f32)
    hgemm_kernel<2><<<dim3(256 / PBN, NTOK / PBM), 256, PSMEM>>>(h2b, w2b, b2, xres, out, 256, 1024);
}

// round 9
// speedup vs baseline: 1.0403x; 1.0403x over previous
#include <cuda_runtime.h>
#include <cuda_bf16.h>
#include <math.h>
#include <stdint.h>

typedef __nv_bfloat16 bf16;

#define NTOK 16384
#define CDIM 256
#define HID  1024

// -------- scratch (__device__ globals; no allocations allowed) --------
__device__ float g_xn     [NTOK * CDIM];
__device__ float g_offattn[NTOK * 256];
__device__ float g_xres   [NTOK * CDIM];
__device__ bf16  g_xnb    [NTOK * CDIM];
__device__ bf16  g_vb     [NTOK * CDIM];
__device__ bf16  g_aggb   [NTOK * CDIM];
__device__ bf16  g_yb     [NTOK * CDIM];
__device__ bf16  g_hb     [NTOK * HID];
__device__ bf16  g_h2b    [NTOK * HID];
__device__ bf16  g_wvb    [256 * 256];
__device__ bf16  g_woutb  [256 * 256];
__device__ bf16  g_w1b    [256 * 1024];
__device__ bf16  g_w2b    [1024 * 256];
__device__ float g_wcat   [256 * 256];
__device__ float g_bcat   [256];

__device__ __forceinline__ float gelu_f(float v) {
    return 0.5f * v * (1.0f + erff(v * 0.7071067811865476f));
}

__device__ __forceinline__ uint32_t smem_u32(const void* p) {
    uint32_t a;
    asm("{ .reg .u64 t; cvta.to.shared.u64 t, %1; cvt.u32.u64 %0, t; }" : "=r"(a) : "l"(p));
    return a;
}

__device__ __forceinline__ uint32_t f2tf32(float f) {
    uint32_t r;
    asm("cvt.rna.tf32.f32 %0, %1;" : "=r"(r) : "f"(f));
    return r;
}

// ---------------- merged weight prep (wcat pre-rounded to tf32) --------------
__global__ void prep_kernel(const float* wv, const float* wout, const float* w1,
                            const float* w2, const float* w_off, const float* w_attn,
                            const float* b_off, const float* b_attn,
                            bf16* wvb, bf16* woutb, bf16* w1b, bf16* w2b,
                            float* wcat, float* bcat) {
    int i = blockIdx.x * 256 + threadIdx.x;
    if (i < 65536) { wvb[i] = __float2bfloat16(wv[i]); return; }
    i -= 65536;
    if (i < 65536) { woutb[i] = __float2bfloat16(wout[i]); return; }
    i -= 65536;
    if (i < 262144) { w1b[i] = __float2bfloat16(w1[i]); return; }
    i -= 262144;
    if (i < 262144) { w2b[i] = __float2bfloat16(w2[i]); return; }
    i -= 262144;
    if (i < 65536) {
        int k = i >> 8, col = i & 255;
        float v = (col < 144) ? w_off[k * 144 + col]
                : (col < 216) ? w_attn[k * 72 + (col - 144)] : 0.f;
        wcat[i] = __uint_as_float(f2tf32(v));
        if (k == 0)
            bcat[col] = (col < 144) ? b_off[col]
                      : (col < 216) ? b_attn[col - 144] : 0.f;
    }
}

// ---------------- LayerNorm1: one block per token, dual output ---------------
__global__ void ln1_kernel(const float* __restrict__ x, const float* __restrict__ g,
                           const float* __restrict__ b, float* __restrict__ yf,
                           bf16* __restrict__ yb) {
    int tok = blockIdx.x;
    int c = threadIdx.x;
    float v = x[(size_t)tok * CDIM + c];
    __shared__ float sh[8];
    float s = v;
    #pragma unroll
    for (int o = 16; o; o >>= 1) s += __shfl_xor_sync(0xffffffffu, s, o);
    if ((c & 31) == 0) sh[c >> 5] = s;
    __syncthreads();
    float tot = 0.f;
    #pragma unroll
    for (int i = 0; i < 8; ++i) tot += sh[i];
    float mean = tot * (1.0f / CDIM);
    __syncthreads();
    float d = v - mean;
    float s2 = d * d;
    #pragma unroll
    for (int o = 16; o; o >>= 1) s2 += __shfl_xor_sync(0xffffffffu, s2, o);
    if ((c & 31) == 0) sh[c >> 5] = s2;
    __syncthreads();
    float v2 = 0.f;
    #pragma unroll
    for (int i = 0; i < 8; ++i) v2 += sh[i];
    float var = v2 * (1.0f / CDIM);
    float out = d * rsqrtf(var + 1e-5f) * g[c] + b[c];
    yf[(size_t)tok * CDIM + c] = __uint_as_float(f2tf32(out));
    yb[(size_t)tok * CDIM + c] = __float2bfloat16(out);
}

// ---------------- tf32 GEMM for off/attn: 64x256x16 tile, 3-stage ------------
#define TFA_STR 20
#define TFB_STR 264
#define TFA_SZ  (64 * TFA_STR * 4)
#define TFB_SZ  (16 * TFB_STR * 4)
#define TF_STG  (TFA_SZ + TFB_SZ)
#define TF_SMEM (3 * TF_STG)

__global__ __launch_bounds__(256)
void tgemm_offattn(const float* __restrict__ A, const float* __restrict__ Bw,
                   const float* __restrict__ bias, float* __restrict__ C) {
    extern __shared__ char sm_[];
    uint32_t S0 = smem_u32(sm_);
    int t = threadIdx.x;
    int lane = t & 31, warp = t >> 5;
    int wm = (warp & 1) * 32;
    int wn = (warp >> 1) * 64;
    int m0 = blockIdx.x * 64;

    int a_row = t >> 2, a_c4 = (t & 3) * 4;
    const float* Ag = A + (size_t)(m0 + a_row) * 256 + a_c4;
    uint32_t a_s = S0 + (a_row * TFA_STR + a_c4) * 4;

    auto prefetch = [&](int it) {
        int st = it % 3;
        const float* ag = Ag + it * 16;
        asm volatile("cp.async.cg.shared.global [%0], [%1], 16;"
                     :: "r"(a_s + st * TF_STG), "l"(ag));
        #pragma unroll
        for (int i = 0; i < 4; ++i) {
            int idx = t + i * 256;
            int row = idx >> 6, c4 = (idx & 63) * 4;
            const float* bg = Bw + (size_t)(it * 16 + row) * 256 + c4;
            uint32_t dst = S0 + TFA_SZ + (row * TFB_STR + c4) * 4 + st * TF_STG;
            asm volatile("cp.async.cg.shared.global [%0], [%1], 16;" :: "r"(dst), "l"(bg));
        }
        asm volatile("cp.async.commit_group;");
    };

    float acc[2][8][4];
    #pragma unroll
    for (int mi = 0; mi < 2; ++mi)
        #pragma unroll
        for (int nj = 0; nj < 8; ++nj)
            #pragma unroll
            for (int r = 0; r < 4; ++r) acc[mi][nj][r] = 0.f;

    const int niter = 16;
    prefetch(0); prefetch(1);

    int lr = lane >> 2, lc = lane & 3;
    for (int it = 0; it < niter; ++it) {
        if (it + 1 < niter) asm volatile("cp.async.wait_group 1;");
        else                asm volatile("cp.async.wait_group 0;");
        __syncthreads();
        if (it + 2 < niter) prefetch(it + 2);

        const uint32_t* As = (const uint32_t*)(sm_ + (it % 3) * TF_STG);
        const uint32_t* Bs = (const uint32_t*)(sm_ + (it % 3) * TF_STG + TFA_SZ);

        #pragma unroll
        for (int kk = 0; kk < 2; ++kk) {
            uint32_t af[2][4];
            #pragma unroll
            for (int mi = 0; mi < 2; ++mi) {
                int rb = wm + mi * 16 + lr;
                af[mi][0] = As[rb * TFA_STR + kk * 8 + lc];
                af[mi][1] = As[(rb + 8) * TFA_STR + kk * 8 + lc];
                af[mi][2] = As[rb * TFA_STR + kk * 8 + lc + 4];
                af[mi][3] = As[(rb + 8) * TFA_STR + kk * 8 + lc + 4];
            }
            #pragma unroll
            for (int nj = 0; nj < 8; ++nj) {
                uint32_t b0 = Bs[(kk * 8 + lc) * TFB_STR + wn + nj * 8 + lr];
                uint32_t b1 = Bs[(kk * 8 + lc + 4) * TFB_STR + wn + nj * 8 + lr];
                #pragma unroll
                for (int mi = 0; mi < 2; ++mi)
                    asm volatile(
                        "mma.sync.aligned.m16n8k8.row.col.f32.tf32.tf32.f32 "
                        "{%0,%1,%2,%3}, {%4,%5,%6,%7}, {%8,%9}, {%0,%1,%2,%3};"
                        : "+f"(acc[mi][nj][0]), "+f"(acc[mi][nj][1]),
                          "+f"(acc[mi][nj][2]), "+f"(acc[mi][nj][3])
                        : "r"(af[mi][0]), "r"(af[mi][1]), "r"(af[mi][2]), "r"(af[mi][3]),
                          "r"(b0), "r"(b1));
            }
        }
    }

    #pragma unroll
    for (int mi = 0; mi < 2; ++mi) {
        #pragma unroll
        for (int nj = 0; nj < 8; ++nj) {
            int r = m0 + wm + mi * 16 + lr;
            int c = wn + nj * 8 + lc * 2;
            float bx = bias[c], by = bias[c + 1];
            float2 v0 = {acc[mi][nj][0] + bx, acc[mi][nj][1] + by};
            float2 v1 = {acc[mi][nj][2] + bx, acc[mi][nj][3] + by};
            *(float2*)(C + (size_t)r * 256 + c) = v0;
            *(float2*)(C + (size_t)(r + 8) * 256 + c) = v1;
        }
    }
}

// ---------------- bf16 mma.sync GEMM: 128x128x32, 3-stage, single sync -------
#define PBM 128
#define PBN 128
#define PBK 32
#define PASTR 80
#define PBSTR 272
#define PA_ST (PBM * PASTR)
#define PB_ST (PBK * PBSTR)
#define PSTG  (PA_ST + PB_ST)
#define PSMEM (3 * PSTG)

template<int EPI>
__global__ __launch_bounds__(256)
void hgemm_kernel(const bf16* __restrict__ A, const bf16* __restrict__ B,
                  const float* __restrict__ bias, const float* __restrict__ resid,
                  void* __restrict__ Cp, int N, int K) {
    extern __shared__ char sm_[];
    uint32_t S0 = smem_u32(sm_);

    int t = threadIdx.x;
    int lane = t & 31, warp = t >> 5;
    int wm = (warp & 3) * 32;
    int wn = (warp >> 2) * 64;
    int m0 = blockIdx.y * PBM;
    int n0 = blockIdx.x * PBN;

    int a_row = t >> 1;
    int a_c16 = (t & 1) * 2;
    const bf16* Ag = A + (size_t)(m0 + a_row) * K + a_c16 * 8;
    uint32_t a_s = S0 + a_row * PASTR + a_c16 * 16;
    int b_row = t >> 3;
    int b_c16 = (t & 7) * 2;
    const bf16* Bg = B + (size_t)b_row * N + n0 + b_c16 * 8;
    uint32_t b_s = S0 + PA_ST + b_row * PBSTR + b_c16 * 16;

    auto prefetch = [&](int chunk) {
        int st = chunk % 3;
        const bf16* ag = Ag + chunk * PBK;
        const bf16* bg = Bg + (size_t)chunk * PBK * N;
        uint32_t sa = a_s + st * PSTG;
        uint32_t sb = b_s + st * PSTG;
        asm volatile("cp.async.cg.shared.global [%0], [%1], 16;" :: "r"(sa), "l"(ag));
        asm volatile("cp.async.cg.shared.global [%0], [%1], 16;" :: "r"(sa + 16), "l"(ag + 8));
        asm volatile("cp.async.cg.shared.global [%0], [%1], 16;" :: "r"(sb), "l"(bg));
        asm volatile("cp.async.cg.shared.global [%0], [%1], 16;" :: "r"(sb + 16), "l"(bg + 8));
        asm volatile("cp.async.commit_group;");
    };

    uint32_t aoff[2], boff[4];
    #pragma unroll
    for (int mi = 0; mi < 2; ++mi)
        aoff[mi] = (wm + mi * 16 + (lane & 15)) * PASTR + (lane >> 4) * 16;
    int tile = lane >> 3;
    #pragma unroll
    for (int ni = 0; ni < 4; ++ni)
        boff[ni] = PA_ST + ((tile & 1) * 8 + (lane & 7)) * PBSTR
                 + (wn + ni * 16 + (tile >> 1) * 8) * 2;

    float acc[2][8][4];
    #pragma unroll
    for (int mi = 0; mi < 2; ++mi)
        #pragma unroll
        for (int nj = 0; nj < 8; ++nj)
            #pragma unroll
            for (int r = 0; r < 4; ++r) acc[mi][nj][r] = 0.f;

    int niter = K / PBK;
    prefetch(0);
    prefetch(1);

    for (int it = 0; it < niter; ++it) {
        if (it + 1 < niter) asm volatile("cp.async.wait_group 1;");
        else                asm volatile("cp.async.wait_group 0;");
        __syncthreads();
        if (it + 2 < niter) prefetch(it + 2);

        uint32_t Sb = S0 + (it % 3) * PSTG;
        #pragma unroll
        for (int kk = 0; kk < 2; ++kk) {
            uint32_t a[2][4];
            #pragma unroll
            for (int mi = 0; mi < 2; ++mi) {
                uint32_t addr = Sb + aoff[mi] + kk * 32;
                asm volatile("ldmatrix.sync.aligned.m8n8.x4.shared.b16 {%0,%1,%2,%3}, [%4];"
                    : "=r"(a[mi][0]), "=r"(a[mi][1]), "=r"(a[mi][2]), "=r"(a[mi][3]) : "r"(addr));
            }
            uint32_t bq[4][4];
            #pragma unroll
            for (int ni = 0; ni < 4; ++ni) {
                uint32_t addr = Sb + boff[ni] + kk * 16 * PBSTR;
                asm volatile("ldmatrix.sync.aligned.m8n8.x4.trans.shared.b16 {%0,%1,%2,%3}, [%4];"
                    : "=r"(bq[ni][0]), "=r"(bq[ni][1]), "=r"(bq[ni][2]), "=r"(bq[ni][3]) : "r"(addr));
            }
            #pragma unroll
            for (int mi = 0; mi < 2; ++mi)
                #pragma unroll
                for (int nj = 0; nj < 8; ++nj) {
                    uint32_t b0 = bq[nj >> 1][(nj & 1) * 2];
                    uint32_t b1 = bq[nj >> 1][(nj & 1) * 2 + 1];
                    asm volatile(
                        "mma.sync.aligned.m16n8k16.row.col.f32.bf16.bf16.f32 "
                        "{%0,%1,%2,%3}, {%4,%5,%6,%7}, {%8,%9}, {%0,%1,%2,%3};"
                        : "+f"(acc[mi][nj][0]), "+f"(acc[mi][nj][1]),
                          "+f"(acc[mi][nj][2]), "+f"(acc[mi][nj][3])
                        : "r"(a[mi][0]), "r"(a[mi][1]), "r"(a[mi][2]), "r"(a[mi][3]),
                          "r"(b0), "r"(b1));
                }
        }
    }

    int r_base = m0 + wm + (lane >> 2);
    int c_base = n0 + wn + (lane & 3) * 2;
    #pragma unroll
    for (int mi = 0; mi < 2; ++mi) {
        #pragma unroll
        for (int nj = 0; nj < 8; ++nj) {
            int r = r_base + mi * 16;
            int c = c_base + nj * 8;
            float bx = bias[c], by = bias[c + 1];
            float o00 = acc[mi][nj][0] + bx;
            float o01 = acc[mi][nj][1] + by;
            float o10 = acc[mi][nj][2] + bx;
            float o11 = acc[mi][nj][3] + by;
            if (EPI == 1) {
                o00 = gelu_f(o00); o01 = gelu_f(o01);
                o10 = gelu_f(o10); o11 = gelu_f(o11);
            }
            if (EPI == 2) {
                const float* rp0 = resid + (size_t)r * N + c;
                const float* rp1 = resid + (size_t)(r + 8) * N + c;
                float* Cf = (float*)Cp;
                float2 v0 = {o00 + rp0[0], o01 + rp0[1]};
                float2 v1 = {o10 + rp1[0], o11 + rp1[1]};
                *(float2*)(Cf + (size_t)r * N + c) = v0;
                *(float2*)(Cf + (size_t)(r + 8) * N + c) = v1;
            } else {
                bf16* Cb = (bf16*)Cp;
                __nv_bfloat162 v0 = {__float2bfloat16(o00), __float2bfloat16(o01)};
                __nv_bfloat162 v1 = {__float2bfloat16(o10), __float2bfloat16(o11)};
                *(__nv_bfloat162*)(Cb + (size_t)r * N + c) = v0;
                *(__nv_bfloat162*)(Cb + (size_t)(r + 8) * N + c) = v1;
            }
        }
    }
}

// ======== fused wout GEMM + residual + LN2: 64x256 tile, LN in epilogue ======
// xres = agg@wout + b_out + x (f32 out); yb = LN2(xres) (bf16 out).
#define QBM 64
#define QASTR 80                    // bytes per A smem row
#define QBSTR 528                   // bytes per B smem row (264 elems)
#define QA_SZ (QBM * QASTR)         // 5120
#define QB_SZ (32 * QBSTR)          // 16896
#define QSTG  (QA_SZ + QB_SZ)       // 22016
#define QLN_SZ (64 * 264 * 4)       // 67584
#define QSMEM (QLN_SZ > 3 * QSTG ? QLN_SZ : 3 * QSTG)

__global__ __launch_bounds__(256)
void hgemm_wout_ln(const bf16* __restrict__ A, const bf16* __restrict__ B,
                   const float* __restrict__ bias, const float* __restrict__ resid,
                   float* __restrict__ xres, const float* __restrict__ g2,
                   const float* __restrict__ b2g, bf16* __restrict__ yb) {
    extern __shared__ char sm_[];
    uint32_t S0 = smem_u32(sm_);
    int t = threadIdx.x;
    int lane = t & 31, warp = t >> 5;
    int wm = (warp & 1) * 32;       // 2 warps along M
    int wn = (warp >> 1) * 64;      // 4 warps along N
    int m0 = blockIdx.x * QBM;

    // A: 64x32 bf16 tile -> 1 chunk/thread
    int a_row = t >> 2, a_c16 = t & 3;
    const bf16* Ag = A + (size_t)(m0 + a_row) * 256 + a_c16 * 8;
    uint32_t a_s = S0 + a_row * QASTR + a_c16 * 16;

    auto prefetch = [&](int ck) {
        int st = ck % 3;
        asm volatile("cp.async.cg.shared.global [%0], [%1], 16;"
                     :: "r"(a_s + st * QSTG), "l"(Ag + ck * 32));
        #pragma unroll
        for (int i = 0; i < 4; ++i) {
            int idx = t + i * 256;
            int row = idx >> 5, c16 = idx & 31;
            const bf16* bg = B + (size_t)(ck * 32 + row) * 256 + c16 * 8;
            uint32_t dst = S0 + st * QSTG + QA_SZ + row * QBSTR + c16 * 16;
            asm volatile("cp.async.cg.shared.global [%0], [%1], 16;" :: "r"(dst), "l"(bg));
        }
        asm volatile("cp.async.commit_group;");
    };

    uint32_t aoff[2], boff[4];
    #pragma unroll
    for (int mi = 0; mi < 2; ++mi)
        aoff[mi] = (wm + mi * 16 + (lane & 15)) * QASTR + (lane >> 4) * 16;
    int tile = lane >> 3;
    #pragma unroll
    for (int ni = 0; ni < 4; ++ni)
        boff[ni] = QA_SZ + ((tile & 1) * 8 + (lane & 7)) * QBSTR
                 + (wn + ni * 16 + (tile >> 1) * 8) * 2;

    float acc[2][8][4];
    #pragma unroll
    for (int mi = 0; mi < 2; ++mi)
        #pragma unroll
        for (int nj = 0; nj < 8; ++nj)
            #pragma unroll
            for (int r = 0; r < 4; ++r) acc[mi][nj][r] = 0.f;

    const int niter = 8;   // K=256 / 32
    prefetch(0); prefetch(1);

    for (int it = 0; it < niter; ++it) {
        if (it + 1 < niter) asm volatile("cp.async.wait_group 1;");
        else                asm volatile("cp.async.wait_group 0;");
        __syncthreads();
        if (it + 2 < niter) prefetch(it + 2);

        uint32_t Sb = S0 + (it % 3) * QSTG;
        #pragma unroll
        for (int kk = 0; kk < 2; ++kk) {
            uint32_t a[2][4];
            #pragma unroll
            for (int mi = 0; mi < 2; ++mi) {
                uint32_t addr = Sb + aoff[mi] + kk * 32;
                asm volatile("ldmatrix.sync.aligned.m8n8.x4.shared.b16 {%0,%1,%2,%3}, [%4];"
                    : "=r"(a[mi][0]), "=r"(a[mi][1]), "=r"(a[mi][2]), "=r"(a[mi][3]) : "r"(addr));
            }
            uint32_t bq[4][4];
            #pragma unroll
            for (int ni = 0; ni < 4; ++ni) {
                uint32_t addr = Sb + boff[ni] + kk * 16 * QBSTR;
                asm volatile("ldmatrix.sync.aligned.m8n8.x4.trans.shared.b16 {%0,%1,%2,%3}, [%4];"
                    : "=r"(bq[ni][0]), "=r"(bq[ni][1]), "=r"(bq[ni][2]), "=r"(bq[ni][3]) : "r"(addr));
            }
            #pragma unroll
            for (int mi = 0; mi < 2; ++mi)
                #pragma unroll
                for (int nj = 0; nj < 8; ++nj) {
                    uint32_t b0 = bq[nj >> 1][(nj & 1) * 2];
                    uint32_t b1 = bq[nj >> 1][(nj & 1) * 2 + 1];
                    asm volatile(
                        "mma.sync.aligned.m16n8k16.row.col.f32.bf16.bf16.f32 "
                        "{%0,%1,%2,%3}, {%4,%5,%6,%7}, {%8,%9}, {%0,%1,%2,%3};"
                        : "+f"(acc[mi][nj][0]), "+f"(acc[mi][nj][1]),
                          "+f"(acc[mi][nj][2]), "+f"(acc[mi][nj][3])
                        : "r"(a[mi][0]), "r"(a[mi][1]), "r"(a[mi][2]), "r"(a[mi][3]),
                          "r"(b0), "r"(b1));
                }
        }
    }

    // all warps done with stage smem before LN tile overwrites it
    __syncthreads();
    float* lt = (float*)sm_;   // [64][264] f32

    int lr0 = wm + (lane >> 2);
    int cb = wn + (lane & 3) * 2;
    #pragma unroll
    for (int mi = 0; mi < 2; ++mi) {
        #pragma unroll
        for (int nj = 0; nj < 8; ++nj) {
            int rl = lr0 + mi * 16;
            int c = cb + nj * 8;
            float bx = bias[c], by = bias[c + 1];
            const float* rp0 = resid + (size_t)(m0 + rl) * 256 + c;
            const float* rp1 = resid + (size_t)(m0 + rl + 8) * 256 + c;
            float2 v0 = {acc[mi][nj][0] + bx + rp0[0], acc[mi][nj][1] + by + rp0[1]};
            float2 v1 = {acc[mi][nj][2] + bx + rp1[0], acc[mi][nj][3] + by + rp1[1]};
            *(float2*)(xres + (size_t)(m0 + rl) * 256 + c) = v0;
            *(float2*)(xres + (size_t)(m0 + rl + 8) * 256 + c) = v1;
            lt[rl * 264 + c] = v0.x;       lt[rl * 264 + c + 1] = v0.y;
            lt[(rl + 8) * 264 + c] = v1.x; lt[(rl + 8) * 264 + c + 1] = v1.y;
        }
    }
    __syncthreads();

    // LN2: warp w handles rows w*8..w*8+7; lane owns cols lane*8..lane*8+7
    int colb = lane * 8;
    float gg[8], bb[8];
    #pragma unroll
    for (int j = 0; j < 8; ++j) { gg[j] = g2[colb + j]; bb[j] = b2g[colb + j]; }

    for (int i = 0; i < 8; ++i) {
        int rr = warp * 8 + i;
        const float* rowp = lt + rr * 264 + colb;
        float v[8];
        float s = 0.f;
        #pragma unroll
        for (int j = 0; j < 8; ++j) { v[j] = rowp[j]; s += v[j]; }
        #pragma unroll
        for (int o = 16; o; o >>= 1) s += __shfl_xor_sync(0xffffffffu, s, o);
        float mean = s * (1.0f / 256.0f);
        float s2 = 0.f;
        #pragma unroll
        for (int j = 0; j < 8; ++j) { float d = v[j] - mean; s2 += d * d; }
        #pragma unroll
        for (int o = 16; o; o >>= 1) s2 += __shfl_xor_sync(0xffffffffu, s2, o);
        float inv = rsqrtf(s2 * (1.0f / 256.0f) + 1e-5f);
        bf16 ob[8];
        #pragma unroll
        for (int j = 0; j < 8; ++j)
            ob[j] = __float2bfloat16((v[j] - mean) * inv * gg[j] + bb[j]);
        *(uint4*)(yb + (size_t)(m0 + rr) * 256 + colb) = *(uint4*)ob;
    }
}

// ---------------- Deformable sampling: one warp = (token, head-pair) ---------
__global__ void sample_kernel(const bf16* __restrict__ v, const float* __restrict__ offattn,
                              const float* __restrict__ rp, bf16* __restrict__ agg) {
    int gw = blockIdx.x * 8 + (threadIdx.x >> 5);
    int lane = threadIdx.x & 31;
    int tg = gw >> 2;
    int head = ((gw & 3) << 1) + (lane >> 4);
    int l16 = lane & 15;
    int bb = tg >> 13;
    int pos = tg & 8191;

    const float* lg = offattn + (size_t)tg * 256 + 144 + head * 9;
    float w[9];
    float mx = -1e30f;
    #pragma unroll
    for (int k = 0; k < 9; ++k) { w[k] = lg[k]; mx = fmaxf(mx, w[k]); }
    float sum = 0.f;
    #pragma unroll
    for (int k = 0; k < 9; ++k) { w[k] = expf(w[k] - mx); sum += w[k]; }
    float inv = 1.0f / sum;

    const float* rpp  = rp + (size_t)pos * 18;
    const float* offp = offattn + (size_t)tg * 256 + head * 18;
    const __nv_bfloat162* vc = (const __nv_bfloat162*)v + head * 16 + l16;
    int base = bb << 13;
    float a0 = 0.f, a1 = 0.f;
    #pragma unroll
    for (int k = 0; k < 9; ++k) {
        float cx = (rpp[k * 2 + 0] + offp[k * 2 + 0] + 1.0f) * 0.5f * 127.0f;
        float cy = (rpp[k * 2 + 1] + offp[k * 2 + 1] + 1.0f) * 0.5f * 63.0f;
        float fx = floorf(cx), fy = floorf(cy);
        float wx = cx - fx, wy = cy - fy;
        int x0 = min(max((int)fx, 0), 127);
        int x1 = min(max((int)fx + 1, 0), 127);
        int y0 = min(max((int)fy, 0), 63);
        int y1 = min(max((int)fy + 1, 0), 63);
        float2 v00 = __bfloat1622float2(vc[(size_t)(base + y0 * 128 + x0) * 128]);
        float2 v01 = __bfloat1622float2(vc[(size_t)(base + y0 * 128 + x1) * 128]);
        float2 v10 = __bfloat1622float2(vc[(size_t)(base + y1 * 128 + x0) * 128]);
        float2 v11 = __bfloat1622float2(vc[(size_t)(base + y1 * 128 + x1) * 128]);
        float w00 = (1.f - wy) * (1.f - wx), w01 = (1.f - wy) * wx;
        float w10 = wy * (1.f - wx),         w11 = wy * wx;
        float wk = w[k] * inv;
        a0 += (v00.x * w00 + v01.x * w01 + v10.x * w10 + v11.x * w11) * wk;
        a1 += (v00.y * w00 + v01.y * w01 + v10.y * w10 + v11.y * w11) * wk;
    }
    __nv_bfloat162 ov = {__float2bfloat16(a0), __float2bfloat16(a1)};
    *(__nv_bfloat162*)(agg + (size_t)tg * 256 + head * 32 + l16 * 2) = ov;
}

// ---------------- Depthwise 3x3 conv: sliding window, 4-way x-split ----------
__global__ void dwconv_kernel(const bf16* __restrict__ h, const float* __restrict__ wdw,
                              const float* __restrict__ bdw, bf16* __restrict__ o) {
    int c2 = blockIdx.x * 256 + threadIdx.x;
    int y = blockIdx.y & 63;
    int seg = blockIdx.y >> 6;
    int bb = blockIdx.z;
    int c = c2 * 2;
    int x0 = seg * 32;

    float w0[9], w1[9];
    #pragma unroll
    for (int i = 0; i < 9; ++i) { w0[i] = wdw[c * 9 + i]; w1[i] = wdw[(c + 1) * 9 + i]; }
    float bb0 = bdw[c], bb1 = bdw[c + 1];

    const __nv_bfloat162* hp = (const __nv_bfloat162*)h;
    size_t base = ((size_t)(bb << 13) + y * 128) * 512 + c2;
    bool hu = (y > 0), hd = (y < 63);
    __nv_bfloat162 zero = __float2bfloat162_rn(0.f);

    __nv_bfloat162 cm[3], cc[3], cn[3];
    {
        size_t p = base + ((x0 + 127) & 127) * 512;
        cm[0] = hu ? hp[p - 65536] : zero; cm[1] = hp[p]; cm[2] = hd ? hp[p + 65536] : zero;
        p = base + x0 * 512;
        cc[0] = hu ? hp[p - 65536] : zero; cc[1] = hp[p]; cc[2] = hd ? hp[p + 65536] : zero;
    }
    bf16* op = o + ((size_t)(bb << 13) + y * 128) * 1024 + c;

    for (int x = x0; x < x0 + 32; ++x) {
        size_t p = base + ((x + 1) & 127) * 512;
        cn[0] = hu ? hp[p - 65536] : zero; cn[1] = hp[p]; cn[2] = hd ? hp[p + 65536] : zero;

        float a0 = bb0, a1 = bb1;
        #pragma unroll
        for (int dy = 0; dy < 3; ++dy) {
            float2 vm = __bfloat1622float2(cm[dy]);
            float2 vc = __bfloat1622float2(cc[dy]);
            float2 vp = __bfloat1622float2(cn[dy]);
            a0 += vm.x * w0[dy * 3 + 0] + vc.x * w0[dy * 3 + 1] + vp.x * w0[dy * 3 + 2];
            a1 += vm.y * w1[dy * 3 + 0] + vc.y * w1[dy * 3 + 1] + vp.y * w1[dy * 3 + 2];
        }
        __nv_bfloat162 ov = {__float2bfloat16(gelu_f(a0)), __float2bfloat16(gelu_f(a1))};
        *(__nv_bfloat162*)(op + (size_t)x * 1024) = ov;

        #pragma unroll
        for (int i = 0; i < 3; ++i) { cm[i] = cc[i]; cc[i] = cn[i]; }
    }
}

// ---------------- launch ----------------
extern "C" void kernel_launch(void* const* d_in, const int* in_sizes, int n_in,
                              void* d_out, int out_size) {
    const float* x      = (const float*)d_in[0];
    const float* rp     = (const float*)d_in[1];
    const float* ln1_g  = (const float*)d_in[2];
    const float* ln1_b  = (const float*)d_in[3];
    const float* w_v    = (const float*)d_in[4];
    const float* b_v    = (const float*)d_in[5];
    const float* w_off  = (const float*)d_in[6];
    const float* b_off  = (const float*)d_in[7];
    const float* w_attn = (const float*)d_in[8];
    const float* b_attn = (const float*)d_in[9];
    const float* w_out  = (const float*)d_in[10];
    const float* b_out  = (const float*)d_in[11];
    const float* ln2_g  = (const float*)d_in[12];
    const float* ln2_b  = (const float*)d_in[13];
    const float* w1     = (const float*)d_in[14];
    const float* b1     = (const float*)d_in[15];
    const float* w_dw   = (const float*)d_in[16];
    const float* b_dw   = (const float*)d_in[17];
    const float* w2     = (const float*)d_in[18];
    const float* b2     = (const float*)d_in[19];
    float* out = (float*)d_out;

    float *xn, *offattn, *xres, *wcat, *bcat;
    bf16 *xnb, *vb, *aggb, *yb, *hb, *h2b, *wvb, *woutb, *w1b, *w2b;
    cudaGetSymbolAddress((void**)&xn,      g_xn);
    cudaGetSymbolAddress((void**)&offattn, g_offattn);
    cudaGetSymbolAddress((void**)&xres,    g_xres);
    cudaGetSymbolAddress((void**)&wcat,    g_wcat);
    cudaGetSymbolAddress((void**)&bcat,    g_bcat);
    cudaGetSymbolAddress((void**)&xnb,     g_xnb);
    cudaGetSymbolAddress((void**)&vb,      g_vb);
    cudaGetSymbolAddress((void**)&aggb,    g_aggb);
    cudaGetSymbolAddress((void**)&yb,      g_yb);
    cudaGetSymbolAddress((void**)&hb,      g_hb);
    cudaGetSymbolAddress((void**)&h2b,     g_h2b);
    cudaGetSymbolAddress((void**)&wvb,     g_wvb);
    cudaGetSymbolAddress((void**)&woutb,   g_woutb);
    cudaGetSymbolAddress((void**)&w1b,     g_w1b);
    cudaGetSymbolAddress((void**)&w2b,     g_w2b);

    cudaFuncSetAttribute(hgemm_kernel<0>, cudaFuncAttributeMaxDynamicSharedMemorySize, PSMEM);
    cudaFuncSetAttribute(hgemm_kernel<1>, cudaFuncAttributeMaxDynamicSharedMemorySize, PSMEM);
    cudaFuncSetAttribute(hgemm_kernel<2>, cudaFuncAttributeMaxDynamicSharedMemorySize, PSMEM);
    cudaFuncSetAttribute(tgemm_offattn,   cudaFuncAttributeMaxDynamicSharedMemorySize, TF_SMEM);
    cudaFuncSetAttribute(hgemm_wout_ln,   cudaFuncAttributeMaxDynamicSharedMemorySize, QSMEM);

    // weight prep
    prep_kernel<<<(655360 + 65536 + 255) / 256, 256>>>(
        w_v, w_out, w1, w2, w_off, w_attn, b_off, b_attn,
        wvb, woutb, w1b, w2b, wcat, bcat);

    // 1. LN1 -> xn (tf32-rounded f32) + xnb (bf16)
    ln1_kernel<<<NTOK, 256>>>(x, ln1_g, ln1_b, xn, xnb);
    // 2. v projection (bf16 TC)
    hgemm_kernel<0><<<dim3(256 / PBN, NTOK / PBM), 256, PSMEM>>>(xnb, wvb, b_v, nullptr, vb, 256, 256);
    // 3. offsets+attn combined (tf32 TC)
    tgemm_offattn<<<NTOK / 64, 256, TF_SMEM>>>(xn, wcat, bcat, offattn);
    // 4. softmax + bilinear sampling + aggregation (head-pair warps)
    sample_kernel<<<NTOK / 2, 256>>>(vb, offattn, rp, aggb);
    // 5. output proj + residual + LN2 fused -> xres (f32) + yb (bf16)
    hgemm_wout_ln<<<NTOK / QBM, 256, QSMEM>>>(aggb, woutb, b_out, x, xres, ln2_g, ln2_b, yb);
    // 6. fc1 + GELU (bf16 TC)
    hgemm_kernel<1><<<dim3(HID / PBN, NTOK / PBM), 256, PSMEM>>>(yb, w1b, b1, nullptr, hb, HID, 256);
    // 7. depthwise conv + GELU
    dwconv_kernel<<<dim3(2, 256, 2), 256>>>(hb, w_dw, b_dw, h2b);
    // 8. fc2 + residual -> out (f32)
    hgemm_kernel<2><<<dim3(256 / PBN, NTOK / PBM), 256, PSMEM>>>(h2b, w2b, b2, xres, out, 256, 1024);
}